// round 1
// baseline (speedup 1.0000x reference)
#include <cuda_runtime.h>
#include <math.h>

// Problem constants (GraphAttentionLayer: B=2, N=2048, D_IN=256, H=8, DH=32)
#define BB   2
#define NN   2048
#define DIN  256
#define HH   8
#define DHH  32
#define MROWS (BB*NN)   // 4096
#define BH    (BB*HH)   // 16

// ---------------- scratch (device globals; no allocation allowed) ----------
__device__ float g_Q[(size_t)BH*NN*DHH];      // (b,h,n,d)
__device__ float g_K[(size_t)BH*NN*DHH];      // (b,h,n,d)
__device__ float g_V[(size_t)BH*NN*DHH];      // (b,h,n,d)
__device__ float g_att[(size_t)BB*NN*HH*DHH]; // (b,n,h,d)

// ---------------- packed f32x2 helpers (PTX-only on sm_103a) ---------------
static __device__ __forceinline__ unsigned long long pk2(float lo, float hi){
    unsigned long long r;
    asm("mov.b64 %0, {%1,%2};" : "=l"(r) : "f"(lo), "f"(hi));
    return r;
}
static __device__ __forceinline__ void upk2(unsigned long long v, float& lo, float& hi){
    asm("mov.b64 {%0,%1}, %2;" : "=f"(lo), "=f"(hi) : "l"(v));
}
static __device__ __forceinline__ unsigned long long ffma2(unsigned long long a, unsigned long long b, unsigned long long c){
    unsigned long long d;
    asm("fma.rn.f32x2 %0, %1, %2, %3;" : "=l"(d) : "l"(a), "l"(b), "l"(c));
    return d;
}
static __device__ __forceinline__ unsigned long long fmul2(unsigned long long a, unsigned long long b){
    unsigned long long d;
    asm("mul.rn.f32x2 %0, %1, %2;" : "=l"(d) : "l"(a), "l"(b));
    return d;
}
static __device__ __forceinline__ unsigned long long fadd2(unsigned long long a, unsigned long long b){
    unsigned long long d;
    asm("add.rn.f32x2 %0, %1, %2;" : "=l"(d) : "l"(a), "l"(b));
    return d;
}

// ---------------- QKV projection: C = X @ W^T, scattered to (b,h,n,d) ------
// grid (MROWS/64, 256/64, 3), block 256. blockIdx.z selects {Wq,Wk,Wv}.
__global__ void __launch_bounds__(256) qkv_kernel(
        const float* __restrict__ X,
        const float* __restrict__ Wq,
        const float* __restrict__ Wk,
        const float* __restrict__ Wv)
{
    const float* W = (blockIdx.z == 0) ? Wq : (blockIdx.z == 1) ? Wk : Wv;
    float* Dst     = (blockIdx.z == 0) ? g_Q : (blockIdx.z == 1) ? g_K : g_V;

    __shared__ float As[32][68];   // [k][row], 68 keeps 16B row alignment
    __shared__ float Ws[32][68];

    const int m0 = blockIdx.x * 64;
    const int n0 = blockIdx.y * 64;
    const int tx = threadIdx.x & 15;
    const int ty = threadIdx.x >> 4;

    float acc[4][4];
    #pragma unroll
    for (int i = 0; i < 4; i++)
        #pragma unroll
        for (int j = 0; j < 4; j++) acc[i][j] = 0.0f;

    for (int k0 = 0; k0 < DIN; k0 += 32) {
        __syncthreads();
        #pragma unroll
        for (int l = threadIdx.x; l < 512; l += 256) {
            int row = l >> 3, c4 = l & 7;
            float4 v = *(const float4*)&X[(size_t)(m0 + row) * DIN + k0 + c4 * 4];
            As[c4*4+0][row] = v.x; As[c4*4+1][row] = v.y;
            As[c4*4+2][row] = v.z; As[c4*4+3][row] = v.w;
            float4 w = *(const float4*)&W[(size_t)(n0 + row) * DIN + k0 + c4 * 4];
            Ws[c4*4+0][row] = w.x; Ws[c4*4+1][row] = w.y;
            Ws[c4*4+2][row] = w.z; Ws[c4*4+3][row] = w.w;
        }
        __syncthreads();
        #pragma unroll
        for (int kk = 0; kk < 32; kk++) {
            float4 a4 = *(const float4*)&As[kk][ty * 4];
            float4 b4 = *(const float4*)&Ws[kk][tx * 4];
            float a[4] = {a4.x, a4.y, a4.z, a4.w};
            float b[4] = {b4.x, b4.y, b4.z, b4.w};
            #pragma unroll
            for (int i = 0; i < 4; i++)
                #pragma unroll
                for (int j = 0; j < 4; j++)
                    acc[i][j] += a[i] * b[j];
        }
    }

    // scatter epilogue: feature o -> (h = o/DH, d = o%DH); row m -> (b, n)
    #pragma unroll
    for (int i = 0; i < 4; i++) {
        int m = m0 + ty * 4 + i;
        int b = m >> 11;          // /N
        int n = m & (NN - 1);
        #pragma unroll
        for (int j = 0; j < 4; j++) {
            int o = n0 + tx * 4 + j;
            int h = o >> 5;
            int d = o & 31;
            Dst[(((size_t)(b * HH + h)) * NN + n) * DHH + d] = acc[i][j];
        }
    }
}

// ---------------- masked flash attention (one thread = one query row) ------
// grid 512 = BH * (N/64), block 64. K/V tiles (32 rows) staged in smem.
__global__ void __launch_bounds__(64) attn_kernel(const float* __restrict__ adj)
{
    const int gid  = blockIdx.x;
    const int tile = gid & 31;       // N/64 = 32 tiles
    const int bh   = gid >> 5;
    const int b    = bh >> 3;        // /H
    const int h    = bh & 7;
    const int qrow = tile * 64 + threadIdx.x;

    __shared__ float Ks[32 * 32];
    __shared__ float Vs[32 * 32];

    const float NEGF = -3.0e38f;
    const float scale = 0.17677669529663687f;   // 1/sqrt(32)

    // q row -> packed registers, pre-scaled
    unsigned long long q2[16];
    {
        const float4* q4 = (const float4*)(g_Q + ((size_t)bh * NN + qrow) * DHH);
        #pragma unroll
        for (int i = 0; i < 8; i++) {
            float4 v = q4[i];
            q2[2*i]   = pk2(v.x * scale, v.y * scale);
            q2[2*i+1] = pk2(v.z * scale, v.w * scale);
        }
    }

    unsigned long long acc2[16];
    #pragma unroll
    for (int i = 0; i < 16; i++) acc2[i] = 0ULL;   // {0.f, 0.f}

    float mrow = NEGF;
    float ssum = 0.0f;

    const float4* adj4 = (const float4*)(adj + ((size_t)b * NN + qrow) * NN);
    const float4* Kg   = (const float4*)g_K + (size_t)bh * NN * (DHH / 4);
    const float4* Vg   = (const float4*)g_V + (size_t)bh * NN * (DHH / 4);
    float4* Ks4 = (float4*)Ks;
    float4* Vs4 = (float4*)Vs;

    for (int t = 0; t < NN / 32; t++) {
        const int m0 = t * 32;
        __syncthreads();
        #pragma unroll
        for (int l = threadIdx.x; l < 256; l += 64) {
            Ks4[l] = Kg[m0 * 8 + l];
            Vs4[l] = Vg[m0 * 8 + l];
        }
        __syncthreads();

        // ---- scores for 32 columns ----
        float sc[32];
        float tmax = NEGF;
        #pragma unroll
        for (int i = 0; i < 8; i++) {
            float4 av = adj4[(m0 >> 2) + i];
            float a4[4] = {av.x, av.y, av.z, av.w};
            #pragma unroll
            for (int cc = 0; cc < 4; cc++) {
                const int c = i * 4 + cc;
                const ulonglong2* kr = (const ulonglong2*)(Ks + c * 32);
                ulonglong2 ka = kr[0], kb = kr[1];
                unsigned long long p0 = fmul2(q2[0], ka.x);
                unsigned long long p1 = fmul2(q2[1], ka.y);
                unsigned long long p2 = fmul2(q2[2], kb.x);
                unsigned long long p3 = fmul2(q2[3], kb.y);
                #pragma unroll
                for (int j = 2; j < 8; j += 2) {
                    ulonglong2 kc = kr[j], kd = kr[j + 1];
                    p0 = ffma2(q2[2*j],     kc.x, p0);
                    p1 = ffma2(q2[2*j + 1], kc.y, p1);
                    p2 = ffma2(q2[2*j + 2], kd.x, p2);
                    p3 = ffma2(q2[2*j + 3], kd.y, p3);
                }
                p0 = fadd2(p0, p1);
                p2 = fadd2(p2, p3);
                p0 = fadd2(p0, p2);
                float lo, hi;
                upk2(p0, lo, hi);
                float d = lo + hi;
                d = (a4[cc] != 0.0f) ? d : NEGF;
                sc[c] = d;
                tmax = fmaxf(tmax, d);
            }
        }

        // ---- online softmax update (skip tiles that are fully masked) ----
        if (tmax > -1.0e37f) {
            float nm = fmaxf(mrow, tmax);
            float f  = __expf(mrow - nm);      // mrow=NEGF -> 0
            ssum *= f;
            unsigned long long f2 = pk2(f, f);
            #pragma unroll
            for (int i = 0; i < 16; i++) acc2[i] = fmul2(acc2[i], f2);

            #pragma unroll
            for (int c = 0; c < 32; c++) {
                float p = __expf(sc[c] - nm);  // masked sc = NEGF -> 0
                ssum += p;
                unsigned long long p2v = pk2(p, p);
                const ulonglong2* vr = (const ulonglong2*)(Vs + c * 32);
                #pragma unroll
                for (int j = 0; j < 8; j++) {
                    ulonglong2 vv = vr[j];
                    acc2[2*j]     = ffma2(p2v, vv.x, acc2[2*j]);
                    acc2[2*j + 1] = ffma2(p2v, vv.y, acc2[2*j + 1]);
                }
            }
            mrow = nm;
        }
    }

    // ---- normalize + write to (b, n, h, d) ----
    const float inv = 1.0f / ssum;
    float4* dst4 = (float4*)(g_att + (((size_t)b * NN + qrow) * HH + h) * DHH);
    #pragma unroll
    for (int i = 0; i < 8; i++) {
        float l0, h0, l1, h1;
        upk2(acc2[2*i],     l0, h0);
        upk2(acc2[2*i + 1], l1, h1);
        dst4[i] = make_float4(l0 * inv, h0 * inv, l1 * inv, h1 * inv);
    }
}

// ---------------- output projection: out = att @ Wo^T + bo -----------------
// grid (MROWS/64, 256/64), block 256.
__global__ void __launch_bounds__(256) oproj_kernel(
        const float* __restrict__ Wo,
        const float* __restrict__ bo,
        float* __restrict__ out)
{
    __shared__ float As[32][68];
    __shared__ float Ws[32][68];

    const int m0 = blockIdx.x * 64;
    const int n0 = blockIdx.y * 64;
    const int tx = threadIdx.x & 15;
    const int ty = threadIdx.x >> 4;

    float acc[4][4];
    #pragma unroll
    for (int i = 0; i < 4; i++)
        #pragma unroll
        for (int j = 0; j < 4; j++) acc[i][j] = 0.0f;

    for (int k0 = 0; k0 < 256; k0 += 32) {
        __syncthreads();
        #pragma unroll
        for (int l = threadIdx.x; l < 512; l += 256) {
            int row = l >> 3, c4 = l & 7;
            float4 v = *(const float4*)&g_att[(size_t)(m0 + row) * 256 + k0 + c4 * 4];
            As[c4*4+0][row] = v.x; As[c4*4+1][row] = v.y;
            As[c4*4+2][row] = v.z; As[c4*4+3][row] = v.w;
            float4 w = *(const float4*)&Wo[(size_t)(n0 + row) * 256 + k0 + c4 * 4];
            Ws[c4*4+0][row] = w.x; Ws[c4*4+1][row] = w.y;
            Ws[c4*4+2][row] = w.z; Ws[c4*4+3][row] = w.w;
        }
        __syncthreads();
        #pragma unroll
        for (int kk = 0; kk < 32; kk++) {
            float4 a4 = *(const float4*)&As[kk][ty * 4];
            float4 b4 = *(const float4*)&Ws[kk][tx * 4];
            float a[4] = {a4.x, a4.y, a4.z, a4.w};
            float b[4] = {b4.x, b4.y, b4.z, b4.w};
            #pragma unroll
            for (int i = 0; i < 4; i++)
                #pragma unroll
                for (int j = 0; j < 4; j++)
                    acc[i][j] += a[i] * b[j];
        }
    }

    const float4 bo4 = *(const float4*)&bo[n0 + tx * 4];
    #pragma unroll
    for (int i = 0; i < 4; i++) {
        int m = m0 + ty * 4 + i;
        float4 r = make_float4(acc[i][0] + bo4.x, acc[i][1] + bo4.y,
                               acc[i][2] + bo4.z, acc[i][3] + bo4.w);
        *(float4*)&out[(size_t)m * 256 + n0 + tx * 4] = r;
    }
}

// ---------------- launch ---------------------------------------------------
extern "C" void kernel_launch(void* const* d_in, const int* in_sizes, int n_in,
                              void* d_out, int out_size)
{
    const float* x   = (const float*)d_in[0];
    const float* adj = (const float*)d_in[1];
    const float* Wq  = (const float*)d_in[2];
    const float* Wk  = (const float*)d_in[3];
    const float* Wv  = (const float*)d_in[4];
    const float* Wo  = (const float*)d_in[5];
    const float* bo  = (const float*)d_in[6];
    float* out = (float*)d_out;

    qkv_kernel<<<dim3(MROWS / 64, 256 / 64, 3), 256>>>(x, Wq, Wk, Wv);
    attn_kernel<<<BH * (NN / 64), 64>>>(adj);
    oproj_kernel<<<dim3(MROWS / 64, 256 / 64), 256>>>(Wo, bo, out);
}